// round 1
// baseline (speedup 1.0000x reference)
#include <cuda_runtime.h>

#define NN     50000
#define EE     800000
#define NHD    4
#define NC     32
#define HC     128
#define NL     3
#define NG     128
#define OUTC   10
#define BN_EPS 1e-5f

// ---------------- static device scratch (no allocations allowed) ----------------
__device__ __align__(16) float g_buf0[NN * HC];
__device__ __align__(16) float g_buf1[NN * HC];
__device__ __align__(16) float g_h[NN * HC];
__device__ float g_as[NN * NHD];
__device__ float g_ad[NN * NHD];
__device__ float g_asum[NN * NHD];
__device__ float g_ew[(EE + NN) * NHD];
__device__ float g_sum[HC];
__device__ float g_sq[HC];

__device__ __forceinline__ float* bufPtr(int b) { return b ? g_buf1 : g_buf0; }

// ---------------- kernels ----------------

// x = embed[x_idx]  -> buf0
__global__ void k_embed(const int* __restrict__ xidx, const float* __restrict__ embed, int N) {
    int gid = blockIdx.x * blockDim.x + threadIdx.x;
    if (gid >= N * HC) return;
    int n = gid >> 7, c = gid & 127;
    g_buf0[gid] = embed[xidx[n] * HC + c];
}

// per-layer prep: init out buffer with gat_b, zero attention sums + BN stat accumulators
__global__ void k_prep(const float* __restrict__ gatb, int l, int outB, int N) {
    int gid = blockIdx.x * blockDim.x + threadIdx.x;
    if (gid < N * HC) bufPtr(outB)[gid] = gatb[l * HC + (gid & 127)];
    if (gid < N * NHD) g_asum[gid] = 0.f;
    if (gid < HC) { g_sum[gid] = 0.f; g_sq[gid] = 0.f; }
}

// BN statistics: 128 threads per block, one channel per thread, coalesced row sweep
__global__ void k_stats(int inB, int N) {
    const float* __restrict__ x = bufPtr(inB);
    int c = threadIdx.x;  // 0..127
    float s = 0.f, s2 = 0.f;
    for (int r = blockIdx.x; r < N; r += gridDim.x) {
        float v = x[r * HC + c];
        s += v;
        s2 += v * v;
    }
    atomicAdd(&g_sum[c], s);
    atomicAdd(&g_sq[c], s2);
}

// Fused per-node: BN-normalize -> Linear(128->32)+ReLU -> GAT proj (32->128)
// -> attention dot products a_src/a_dst. All weights in SMEM.
__global__ void k_node(int inB, int l,
                       const float* __restrict__ linW, const float* __restrict__ linb,
                       const float* __restrict__ gatW,
                       const float* __restrict__ attS, const float* __restrict__ attD,
                       const float* __restrict__ bng, const float* __restrict__ bnb,
                       int N) {
    __shared__ float sLin[NC * HC];   // lin_W[l]: [32][128]
    __shared__ float sGat[HC * NC];   // gat_W[l]: [128][32]
    __shared__ float sScale[HC], sShift[HC], sAsW[HC], sAdW[HC], sLb[NC];
    int tid = threadIdx.x;
    for (int i = tid; i < NC * HC; i += blockDim.x) {
        sLin[i] = linW[l * NC * HC + i];
        sGat[i] = gatW[l * HC * NC + i];
    }
    if (tid < HC) {
        float invN = 1.0f / (float)N;
        float mean = g_sum[tid] * invN;
        float var  = g_sq[tid] * invN - mean * mean;
        float rstd = rsqrtf(var + BN_EPS);
        float sc = bng[l * HC + tid] * rstd;
        sScale[tid] = sc;
        sShift[tid] = bnb[l * HC + tid] - sc * mean;
        sAsW[tid] = attS[l * HC + tid];
        sAdW[tid] = attD[l * HC + tid];
    }
    if (tid < NC) sLb[tid] = linb[l * NC + tid];
    __syncthreads();

    int n = blockIdx.x * blockDim.x + tid;
    if (n >= N) return;
    const float* __restrict__ x = bufPtr(inB) + n * HC;

    float y[NC];
#pragma unroll
    for (int c = 0; c < NC; c++) y[c] = sLb[c];
    for (int k = 0; k < HC; k++) {
        float xk = fmaf(x[k], sScale[k], sShift[k]);
#pragma unroll
        for (int c = 0; c < NC; c++) y[c] = fmaf(xk, sLin[c * HC + k], y[c]);
    }
#pragma unroll
    for (int c = 0; c < NC; c++) y[c] = fmaxf(y[c], 0.f);

    for (int hd = 0; hd < NHD; hd++) {
        float as = 0.f, ad = 0.f;
        for (int j = 0; j < NC; j++) {
            int row = hd * NC + j;
            float hv = 0.f;
#pragma unroll
            for (int c = 0; c < NC; c++) hv = fmaf(y[c], sGat[row * NC + c], hv);
            g_h[n * HC + row] = hv;
            as = fmaf(hv, sAsW[row], as);
            ad = fmaf(hv, sAdW[row], ad);
        }
        g_as[n * NHD + hd] = as;
        g_ad[n * NHD + hd] = ad;
    }
}

// edge pass 1: per (edge, head): w = exp(leaky_relu(a_src[s]+a_dst[d])); sum into dst
__global__ void k_edgew(const int* __restrict__ ei, int N, int E) {
    int gid = blockIdx.x * blockDim.x + threadIdx.x;
    int tot = (E + N) * NHD;
    if (gid >= tot) return;
    int e = gid >> 2, hd = gid & 3;
    int s, d;
    if (e < E) { s = ei[e]; d = ei[E + e]; }
    else       { s = d = e - E; }
    float z = g_as[s * NHD + hd] + g_ad[d * NHD + hd];
    z = (z > 0.f) ? z : 0.2f * z;
    float w = __expf(z);
    g_ew[gid] = w;
    atomicAdd(&g_asum[d * NHD + hd], w);
}

// edge pass 2: one warp per edge; lanes cover 128 channels as float4;
// msg = h[src] * alpha scattered to out[dst] with vector atomics.
__global__ void k_agg(const int* __restrict__ ei, int outB, int N, int E) {
    int gid = blockIdx.x * blockDim.x + threadIdx.x;
    int tot = (E + N) * 32;
    if (gid >= tot) return;
    int e = gid >> 5, lane = gid & 31;
    int s, d;
    if (e < E) { s = ei[e]; d = ei[E + e]; }
    else       { s = d = e - E; }
    int hd = lane >> 3;  // 8 lanes (32 channels) per head
    float alpha = g_ew[e * NHD + hd] / (g_asum[d * NHD + hd] + 1e-16f);
    const float4 hv = *reinterpret_cast<const float4*>(&g_h[s * HC + lane * 4]);
    float4 m = make_float4(hv.x * alpha, hv.y * alpha, hv.z * alpha, hv.w * alpha);
    atomicAdd(reinterpret_cast<float4*>(bufPtr(outB) + d * HC + lane * 4), m);
}

__global__ void k_zero_out(float* __restrict__ out, int n) {
    int gid = blockIdx.x * blockDim.x + threadIdx.x;
    if (gid < n) out[gid] = 0.f;
}

// readout: per node, y = x @ W^T + b (10 outputs), scatter-add into graph bucket
__global__ void k_readout(const float* __restrict__ rW, const float* __restrict__ rb,
                          const int* __restrict__ batch, float* __restrict__ out,
                          int inB, int N) {
    __shared__ float sW[OUTC * HC];
    __shared__ float sb[OUTC];
    int tid = threadIdx.x;
    for (int i = tid; i < OUTC * HC; i += blockDim.x) sW[i] = rW[i];
    if (tid < OUTC) sb[tid] = rb[tid];
    __syncthreads();
    int n = blockIdx.x * blockDim.x + tid;
    if (n >= N) return;
    const float* __restrict__ x = bufPtr(inB) + n * HC;
    float acc[OUTC];
#pragma unroll
    for (int o = 0; o < OUTC; o++) acc[o] = sb[o];
    for (int k = 0; k < HC; k++) {
        float xk = x[k];
#pragma unroll
        for (int o = 0; o < OUTC; o++) acc[o] = fmaf(xk, sW[o * HC + k], acc[o]);
    }
    int g = batch[n];
#pragma unroll
    for (int o = 0; o < OUTC; o++) atomicAdd(&out[g * OUTC + o], acc[o]);
}

// ---------------- launch ----------------
extern "C" void kernel_launch(void* const* d_in, const int* in_sizes, int n_in,
                              void* d_out, int out_size) {
    const int*   xidx  = (const int*)d_in[0];
    const int*   ei    = (const int*)d_in[1];
    const int*   batch = (const int*)d_in[2];
    const float* embed = (const float*)d_in[3];
    const float* bng   = (const float*)d_in[4];
    const float* bnb   = (const float*)d_in[5];
    const float* linW  = (const float*)d_in[6];
    const float* linb  = (const float*)d_in[7];
    const float* gatW  = (const float*)d_in[8];
    const float* attS  = (const float*)d_in[9];
    const float* attD  = (const float*)d_in[10];
    const float* gatb  = (const float*)d_in[11];
    const float* rW    = (const float*)d_in[12];
    const float* rb    = (const float*)d_in[13];
    float* out = (float*)d_out;

    int N = in_sizes[0];
    int E = in_sizes[1] / 2;

    k_embed<<<(N * HC + 255) / 256, 256>>>(xidx, embed, N);

    for (int l = 0; l < NL; l++) {
        int inB = l & 1;
        int outB = inB ^ 1;
        k_prep<<<(N * HC + 255) / 256, 256>>>(gatb, l, outB, N);
        k_stats<<<256, 128>>>(inB, N);
        k_node<<<(N + 127) / 128, 128>>>(inB, l, linW, linb, gatW, attS, attD, bng, bnb, N);
        int totW = (E + N) * NHD;
        k_edgew<<<(totW + 255) / 256, 256>>>(ei, N, E);
        int totA = (E + N) * 32;
        k_agg<<<(totA + 255) / 256, 256>>>(ei, outB, N, E);
    }

    k_zero_out<<<(out_size + 255) / 256, 256>>>(out, out_size);
    k_readout<<<(N + 127) / 128, 128>>>(rW, rb, batch, out, 1, N);
}

// round 3
// speedup vs baseline: 1.4791x; 1.4791x over previous
#include <cuda_runtime.h>

#define NN     50000
#define EE     800000
#define TOTE   (EE + NN)
#define NHD    4
#define NC     32
#define HC     128
#define NL     3
#define NG     128
#define OUTC   10
#define BN_EPS 1e-5f

// ---------------- static device scratch ----------------
__device__ __align__(16) float g_buf0[NN * HC];
__device__ __align__(16) float g_buf1[NN * HC];
__device__ __align__(16) float g_h[NN * HC];
__device__ __align__(16) float g_as[NN * NHD];
__device__ __align__(16) float g_ad[NN * NHD];
__device__ float g_sum[HC];
__device__ float g_sq[HC];
__device__ int   g_deg[NN];
__device__ int   g_off[NN + 1];
__device__ int   g_cur[NN];
__device__ int   g_csrc[TOTE];

__device__ __forceinline__ float* bufPtr(int b) { return b ? g_buf1 : g_buf0; }

// ---------------- kernels ----------------

// x = embed[x_idx] -> buf0; also zero BN stats and degree array
__global__ void k_embed(const int* __restrict__ xidx, const float* __restrict__ embed, int N) {
    int gid = blockIdx.x * blockDim.x + threadIdx.x;
    if (gid < HC) { g_sum[gid] = 0.f; g_sq[gid] = 0.f; }
    if (gid < N) g_deg[gid] = 0;
    if (gid >= N * HC) return;
    int n = gid >> 7, c = gid & 127;
    g_buf0[gid] = embed[xidx[n] * HC + c];
}

// degree histogram over edges + self loops
__global__ void k_hist(const int* __restrict__ ei, int N, int E) {
    int gid = blockIdx.x * blockDim.x + threadIdx.x;
    if (gid >= E + N) return;
    int d = (gid < E) ? ei[E + gid] : (gid - E);
    atomicAdd(&g_deg[d], 1);
}

// single-block exclusive scan of degrees -> offsets (+ cursor copy)
__global__ void k_scan(int N) {
    __shared__ int ssum[1024];
    int t = threadIdx.x;
    int CH = (N + 1023) / 1024;
    int b = t * CH, e = min(b + CH, N);
    int s = 0;
    for (int i = b; i < e; i++) s += g_deg[i];
    ssum[t] = s;
    __syncthreads();
    for (int off = 1; off < 1024; off <<= 1) {
        int v = (t >= off) ? ssum[t - off] : 0;
        __syncthreads();
        ssum[t] += v;
        __syncthreads();
    }
    int run = ssum[t] - s;
    for (int i = b; i < e; i++) {
        g_off[i] = run;
        g_cur[i] = run;
        run += g_deg[i];
    }
    if (t == 1023) g_off[N] = run;
}

// scatter edge sources into CSR buckets
__global__ void k_scatter(const int* __restrict__ ei, int N, int E) {
    int gid = blockIdx.x * blockDim.x + threadIdx.x;
    if (gid >= E + N) return;
    int s, d;
    if (gid < E) { s = ei[gid]; d = ei[E + gid]; }
    else         { s = d = gid - E; }
    int pos = atomicAdd(&g_cur[d], 1);
    g_csrc[pos] = s;
}

// BN statistics: one channel per thread, coalesced row sweep
__global__ void k_stats(int inB, int N) {
    const float* __restrict__ x = bufPtr(inB);
    int c = threadIdx.x;  // 0..127
    float s = 0.f, s2 = 0.f;
    for (int r = blockIdx.x; r < N; r += gridDim.x) {
        float v = x[r * HC + c];
        s += v;
        s2 += v * v;
    }
    atomicAdd(&g_sum[c], s);
    atomicAdd(&g_sq[c], s2);
}

// Fused per-node: BN -> Linear(128->32)+ReLU -> GAT proj (32->128) -> attention dots.
// SMEM union: region A = sLin (phase 1). region B = staging tile (phase 1) / sGatT (phase 2).
#define SXP 129
__global__ void __launch_bounds__(128)
k_node(int inB, int l,
       const float* __restrict__ linW, const float* __restrict__ linb,
       const float* __restrict__ gatW,
       const float* __restrict__ attS, const float* __restrict__ attD,
       const float* __restrict__ bng, const float* __restrict__ bnb,
       int N) {
    __shared__ __align__(16) float sA[NC * HC];        // sLin [c][k] (phase 1)
    __shared__ __align__(16) float sB[32 * SXP];       // sX[k][node] p1  /  sGatT [c][r] p2
    __shared__ float sScale[HC], sShift[HC];
    __shared__ float sAttS[HC], sAttD[HC], sLb[NC];

    int tid = threadIdx.x;
    for (int i = tid; i < NC * HC; i += 128) sA[i] = linW[l * NC * HC + i];
    if (tid < HC) {
        float invN = 1.0f / (float)N;
        float mean = g_sum[tid] * invN;
        float var  = g_sq[tid] * invN - mean * mean;
        float rstd = rsqrtf(var + BN_EPS);
        float sc = bng[l * HC + tid] * rstd;
        sScale[tid] = sc;
        sShift[tid] = bnb[l * HC + tid] - sc * mean;
        sAttS[tid] = attS[l * HC + tid];
        sAttD[tid] = attD[l * HC + tid];
    }
    if (tid < NC) sLb[tid] = linb[l * NC + tid];

    int n0 = blockIdx.x * 128;
    int n = n0 + tid;
    const float* __restrict__ xb = bufPtr(inB);

    float y[NC];
#pragma unroll
    for (int c = 0; c < NC; c++) y[c] = sLb[c];

    // -------- phase 1: BN + Linear(128->32), k-tiled --------
#pragma unroll
    for (int kt = 0; kt < 4; kt++) {
        __syncthreads();
        // stage 128 nodes x 32 channels into transposed tile, coalesced global reads
#pragma unroll
        for (int j = 0; j < 32; j++) {
            int i = tid + j * 128;
            int ni = i >> 5, ki = i & 31;
            int k = kt * 32 + ki;
            int nn = n0 + ni;
            float v = (nn < N) ? xb[nn * HC + k] : 0.f;
            sB[ki * SXP + ni] = fmaf(v, sScale[k], sShift[k]);
        }
        __syncthreads();
        float xk[32];
#pragma unroll
        for (int kk = 0; kk < 32; kk++) xk[kk] = sB[kk * SXP + tid];
#pragma unroll
        for (int c = 0; c < NC; c++) {
            const float4* w4 = reinterpret_cast<const float4*>(&sA[c * HC + kt * 32]);
            float acc = y[c];
#pragma unroll
            for (int q = 0; q < 8; q++) {
                float4 w = w4[q];
                acc = fmaf(xk[4 * q], w.x, acc);
                acc = fmaf(xk[4 * q + 1], w.y, acc);
                acc = fmaf(xk[4 * q + 2], w.z, acc);
                acc = fmaf(xk[4 * q + 3], w.w, acc);
            }
            y[c] = acc;
        }
    }
#pragma unroll
    for (int c = 0; c < NC; c++) y[c] = fmaxf(y[c], 0.f);

    // -------- phase 2: GAT projection (32->128) + attention dots --------
    __syncthreads();
    // load gat_W transposed into sB as sGatT[c][r]; output-indexed => conflict-free smem writes
    for (int o = tid; o < NC * HC; o += 128) {
        int c = o >> 7, r = o & 127;                 // sGatT index = c*128 + r
        sB[o] = __ldg(&gatW[l * NC * HC + r * NC + c]);
    }
    __syncthreads();

    if (n < N) {
        float as[NHD] = {0.f, 0.f, 0.f, 0.f};
        float ad[NHD] = {0.f, 0.f, 0.f, 0.f};
#pragma unroll
        for (int r4 = 0; r4 < HC; r4 += 4) {
            float4 h4 = make_float4(0.f, 0.f, 0.f, 0.f);
#pragma unroll
            for (int c = 0; c < NC; c++) {
                float yc = y[c];
                const float4 w = *reinterpret_cast<const float4*>(&sB[c * HC + r4]);
                h4.x = fmaf(yc, w.x, h4.x);
                h4.y = fmaf(yc, w.y, h4.y);
                h4.z = fmaf(yc, w.z, h4.z);
                h4.w = fmaf(yc, w.w, h4.w);
            }
            *reinterpret_cast<float4*>(&g_h[n * HC + r4]) = h4;
            int hd = r4 >> 5;
            const float4 s4 = *reinterpret_cast<const float4*>(&sAttS[r4]);
            const float4 d4 = *reinterpret_cast<const float4*>(&sAttD[r4]);
            as[hd] += h4.x * s4.x + h4.y * s4.y + h4.z * s4.z + h4.w * s4.w;
            ad[hd] += h4.x * d4.x + h4.y * d4.y + h4.z * d4.z + h4.w * d4.w;
        }
        *reinterpret_cast<float4*>(&g_as[n * NHD]) = make_float4(as[0], as[1], as[2], as[3]);
        *reinterpret_cast<float4*>(&g_ad[n * NHD]) = make_float4(ad[0], ad[1], ad[2], ad[3]);
    }
}

// Gather: one warp per dst node. Fused edge softmax + weighted aggregation, no atomics.
// Block 0 also zeroes BN stat accumulators for the next layer.
__global__ void k_gather(int outB, const float* __restrict__ gatb, int l, int N) {
    if (blockIdx.x == 0 && threadIdx.x < HC) {
        g_sum[threadIdx.x] = 0.f;
        g_sq[threadIdx.x] = 0.f;
    }
    int gw = (blockIdx.x * blockDim.x + threadIdx.x) >> 5;
    int lane = threadIdx.x & 31;
    if (gw >= N) return;
    int hd = lane >> 3;
    int start = g_off[gw], end = g_off[gw + 1];
    float adv = __ldg(&g_ad[gw * NHD + hd]);
    float4 acc = make_float4(0.f, 0.f, 0.f, 0.f);
    float wsum = 0.f;
    for (int base = start; base < end; base += 32) {
        int cnt = min(32, end - base);
        int s_l = (lane < cnt) ? g_csrc[base + lane] : 0;
        for (int j = 0; j < cnt; j++) {
            int s = __shfl_sync(0xffffffffu, s_l, j);
            float av = __ldg(&g_as[s * NHD + hd]);
            float z = av + adv;
            z = (z > 0.f) ? z : 0.2f * z;
            float w = __expf(z);
            wsum += w;
            const float4 hv = *reinterpret_cast<const float4*>(&g_h[s * HC + lane * 4]);
            acc.x = fmaf(w, hv.x, acc.x);
            acc.y = fmaf(w, hv.y, acc.y);
            acc.z = fmaf(w, hv.z, acc.z);
            acc.w = fmaf(w, hv.w, acc.w);
        }
    }
    float inv = 1.f / (wsum + 1e-16f);
    const float4 b4 = *reinterpret_cast<const float4*>(&gatb[l * HC + lane * 4]);
    float4 o = make_float4(fmaf(acc.x, inv, b4.x), fmaf(acc.y, inv, b4.y),
                           fmaf(acc.z, inv, b4.z), fmaf(acc.w, inv, b4.w));
    *reinterpret_cast<float4*>(bufPtr(outB) + gw * HC + lane * 4) = o;
}

__global__ void k_zero_out(float* __restrict__ out, int n) {
    int gid = blockIdx.x * blockDim.x + threadIdx.x;
    if (gid < n) out[gid] = 0.f;
}

// readout: y = x @ W^T + b, scatter-add into graph bucket
__global__ void k_readout(const float* __restrict__ rW, const float* __restrict__ rb,
                          const int* __restrict__ batch, float* __restrict__ out,
                          int inB, int N) {
    __shared__ float sW[OUTC * HC];
    __shared__ float sb[OUTC];
    int tid = threadIdx.x;
    for (int i = tid; i < OUTC * HC; i += blockDim.x) sW[i] = rW[i];
    if (tid < OUTC) sb[tid] = rb[tid];
    __syncthreads();
    int n = blockIdx.x * blockDim.x + tid;
    if (n >= N) return;
    const float* __restrict__ x = bufPtr(inB) + n * HC;
    float acc[OUTC];
#pragma unroll
    for (int o = 0; o < OUTC; o++) acc[o] = sb[o];
    for (int k = 0; k < HC; k++) {
        float xk = x[k];
#pragma unroll
        for (int o = 0; o < OUTC; o++) acc[o] = fmaf(xk, sW[o * HC + k], acc[o]);
    }
    int g = batch[n];
#pragma unroll
    for (int o = 0; o < OUTC; o++) atomicAdd(&out[g * OUTC + o], acc[o]);
}

// ---------------- launch ----------------
extern "C" void kernel_launch(void* const* d_in, const int* in_sizes, int n_in,
                              void* d_out, int out_size) {
    const int*   xidx  = (const int*)d_in[0];
    const int*   ei    = (const int*)d_in[1];
    const int*   batch = (const int*)d_in[2];
    const float* embed = (const float*)d_in[3];
    const float* bng   = (const float*)d_in[4];
    const float* bnb   = (const float*)d_in[5];
    const float* linW  = (const float*)d_in[6];
    const float* linb  = (const float*)d_in[7];
    const float* gatW  = (const float*)d_in[8];
    const float* attS  = (const float*)d_in[9];
    const float* attD  = (const float*)d_in[10];
    const float* gatb  = (const float*)d_in[11];
    const float* rW    = (const float*)d_in[12];
    const float* rb    = (const float*)d_in[13];
    float* out = (float*)d_out;

    int N = in_sizes[0];
    int E = in_sizes[1] / 2;
    int tot = E + N;

    k_embed<<<(N * HC + 255) / 256, 256>>>(xidx, embed, N);
    k_hist<<<(tot + 255) / 256, 256>>>(ei, N, E);
    k_scan<<<1, 1024>>>(N);
    k_scatter<<<(tot + 255) / 256, 256>>>(ei, N, E);

    for (int l = 0; l < NL; l++) {
        int inB = l & 1;
        int outB = inB ^ 1;
        k_stats<<<592, 128>>>(inB, N);
        k_node<<<(N + 127) / 128, 128>>>(inB, l, linW, linb, gatW, attS, attD, bng, bnb, N);
        k_gather<<<(N * 32 + 255) / 256, 256>>>(outB, gatb, l, N);
    }

    k_zero_out<<<(out_size + 255) / 256, 256>>>(out, out_size);
    k_readout<<<(N + 127) / 128, 128>>>(rW, rb, batch, out, 1, N);
}

// round 4
// speedup vs baseline: 1.5481x; 1.0467x over previous
#include <cuda_runtime.h>

#define NN     50000
#define EE     800000
#define TOTE   (EE + NN)
#define NHD    4
#define NC     32
#define HC     128
#define NL     3
#define NG     128
#define OUTC   10
#define BN_EPS 1e-5f

// ---------------- static device scratch ----------------
__device__ __align__(16) float g_buf0[NN * HC];
__device__ __align__(16) float g_buf1[NN * HC];
__device__ __align__(16) float g_h[NN * HC];
__device__ __align__(16) float g_as[NN * NHD];
__device__ __align__(16) float g_ad[NN * NHD];
__device__ float g_sum[HC];
__device__ float g_sq[HC];
__device__ int   g_deg[NN];
__device__ int   g_off[NN + 1];
__device__ int   g_cur[NN];
__device__ int   g_csrc[TOTE];

__device__ __forceinline__ float* bufPtr(int b) { return b ? g_buf1 : g_buf0; }

// ---------------- kernels ----------------

// x = embed[x_idx] -> buf0; also zero BN stats and degree array
__global__ void k_embed(const int* __restrict__ xidx, const float* __restrict__ embed, int N) {
    int gid = blockIdx.x * blockDim.x + threadIdx.x;
    if (gid < HC) { g_sum[gid] = 0.f; g_sq[gid] = 0.f; }
    if (gid < N) g_deg[gid] = 0;
    if (gid >= N * HC) return;
    int n = gid >> 7, c = gid & 127;
    g_buf0[gid] = embed[xidx[n] * HC + c];
}

// degree histogram over edges + self loops
__global__ void k_hist(const int* __restrict__ ei, int N, int E) {
    int gid = blockIdx.x * blockDim.x + threadIdx.x;
    if (gid >= E + N) return;
    int d = (gid < E) ? ei[E + gid] : (gid - E);
    atomicAdd(&g_deg[d], 1);
}

// single-block exclusive scan of degrees -> offsets (+ cursor copy); also zeros d_out
__global__ void k_scan(int N, float* __restrict__ out, int out_n) {
    __shared__ int ssum[1024];
    int t = threadIdx.x;
    for (int i = t; i < out_n; i += 1024) out[i] = 0.f;
    int CH = (N + 1023) / 1024;
    int b = t * CH, e = min(b + CH, N);
    int s = 0;
    for (int i = b; i < e; i++) s += g_deg[i];
    ssum[t] = s;
    __syncthreads();
    for (int off = 1; off < 1024; off <<= 1) {
        int v = (t >= off) ? ssum[t - off] : 0;
        __syncthreads();
        ssum[t] += v;
        __syncthreads();
    }
    int run = ssum[t] - s;
    for (int i = b; i < e; i++) {
        g_off[i] = run;
        g_cur[i] = run;
        run += g_deg[i];
    }
    if (t == 1023) g_off[N] = run;
}

// scatter edge sources into CSR buckets
__global__ void k_scatter(const int* __restrict__ ei, int N, int E) {
    int gid = blockIdx.x * blockDim.x + threadIdx.x;
    if (gid >= E + N) return;
    int s, d;
    if (gid < E) { s = ei[gid]; d = ei[E + gid]; }
    else         { s = d = gid - E; }
    int pos = atomicAdd(&g_cur[d], 1);
    g_csrc[pos] = s;
}

// BN statistics: one channel per thread, coalesced row sweep
__global__ void k_stats(int inB, int N) {
    const float* __restrict__ x = bufPtr(inB);
    int c = threadIdx.x;  // 0..127
    float s = 0.f, s2 = 0.f;
    for (int r = blockIdx.x; r < N; r += gridDim.x) {
        float v = x[r * HC + c];
        s += v;
        s2 += v * v;
    }
    atomicAdd(&g_sum[c], s);
    atomicAdd(&g_sq[c], s2);
}

// Fused per-node: BN -> Linear(128->32)+ReLU -> GAT proj (32->128) -> attention dots.
// (validated in R3 — unchanged)
#define SXP 129
__global__ void __launch_bounds__(128)
k_node(int inB, int l,
       const float* __restrict__ linW, const float* __restrict__ linb,
       const float* __restrict__ gatW,
       const float* __restrict__ attS, const float* __restrict__ attD,
       const float* __restrict__ bng, const float* __restrict__ bnb,
       int N) {
    __shared__ __align__(16) float sA[NC * HC];        // sLin [c][k] (phase 1)
    __shared__ __align__(16) float sB[32 * SXP];       // sX[k][node] p1  /  sGatT [c][r] p2
    __shared__ float sScale[HC], sShift[HC];
    __shared__ float sAttS[HC], sAttD[HC], sLb[NC];

    int tid = threadIdx.x;
    for (int i = tid; i < NC * HC; i += 128) sA[i] = linW[l * NC * HC + i];
    if (tid < HC) {
        float invN = 1.0f / (float)N;
        float mean = g_sum[tid] * invN;
        float var  = g_sq[tid] * invN - mean * mean;
        float rstd = rsqrtf(var + BN_EPS);
        float sc = bng[l * HC + tid] * rstd;
        sScale[tid] = sc;
        sShift[tid] = bnb[l * HC + tid] - sc * mean;
        sAttS[tid] = attS[l * HC + tid];
        sAttD[tid] = attD[l * HC + tid];
    }
    if (tid < NC) sLb[tid] = linb[l * NC + tid];

    int n0 = blockIdx.x * 128;
    int n = n0 + tid;
    const float* __restrict__ xb = bufPtr(inB);

    float y[NC];
#pragma unroll
    for (int c = 0; c < NC; c++) y[c] = sLb[c];

#pragma unroll
    for (int kt = 0; kt < 4; kt++) {
        __syncthreads();
#pragma unroll
        for (int j = 0; j < 32; j++) {
            int i = tid + j * 128;
            int ni = i >> 5, ki = i & 31;
            int k = kt * 32 + ki;
            int nn = n0 + ni;
            float v = (nn < N) ? xb[nn * HC + k] : 0.f;
            sB[ki * SXP + ni] = fmaf(v, sScale[k], sShift[k]);
        }
        __syncthreads();
        float xk[32];
#pragma unroll
        for (int kk = 0; kk < 32; kk++) xk[kk] = sB[kk * SXP + tid];
#pragma unroll
        for (int c = 0; c < NC; c++) {
            const float4* w4 = reinterpret_cast<const float4*>(&sA[c * HC + kt * 32]);
            float acc = y[c];
#pragma unroll
            for (int q = 0; q < 8; q++) {
                float4 w = w4[q];
                acc = fmaf(xk[4 * q], w.x, acc);
                acc = fmaf(xk[4 * q + 1], w.y, acc);
                acc = fmaf(xk[4 * q + 2], w.z, acc);
                acc = fmaf(xk[4 * q + 3], w.w, acc);
            }
            y[c] = acc;
        }
    }
#pragma unroll
    for (int c = 0; c < NC; c++) y[c] = fmaxf(y[c], 0.f);

    __syncthreads();
    for (int o = tid; o < NC * HC; o += 128) {
        int c = o >> 7, r = o & 127;
        sB[o] = __ldg(&gatW[l * NC * HC + r * NC + c]);
    }
    __syncthreads();

    if (n < N) {
        float as[NHD] = {0.f, 0.f, 0.f, 0.f};
        float ad[NHD] = {0.f, 0.f, 0.f, 0.f};
#pragma unroll
        for (int r4 = 0; r4 < HC; r4 += 4) {
            float4 h4 = make_float4(0.f, 0.f, 0.f, 0.f);
#pragma unroll
            for (int c = 0; c < NC; c++) {
                float yc = y[c];
                const float4 w = *reinterpret_cast<const float4*>(&sB[c * HC + r4]);
                h4.x = fmaf(yc, w.x, h4.x);
                h4.y = fmaf(yc, w.y, h4.y);
                h4.z = fmaf(yc, w.z, h4.z);
                h4.w = fmaf(yc, w.w, h4.w);
            }
            *reinterpret_cast<float4*>(&g_h[n * HC + r4]) = h4;
            int hd = r4 >> 5;
            const float4 s4 = *reinterpret_cast<const float4*>(&sAttS[r4]);
            const float4 d4 = *reinterpret_cast<const float4*>(&sAttD[r4]);
            as[hd] += h4.x * s4.x + h4.y * s4.y + h4.z * s4.z + h4.w * s4.w;
            ad[hd] += h4.x * d4.x + h4.y * d4.y + h4.z * d4.z + h4.w * d4.w;
        }
        *reinterpret_cast<float4*>(&g_as[n * NHD]) = make_float4(as[0], as[1], as[2], as[3]);
        *reinterpret_cast<float4*>(&g_ad[n * NHD]) = make_float4(ad[0], ad[1], ad[2], ad[3]);
    }
}

// Gather: warp per dst node. Lane-parallel weight phase + unrolled, MLP-rich consume phase.
__device__ __forceinline__ float lrelu_exp(float z) {
    z = (z > 0.f) ? z : 0.2f * z;
    return __expf(z);
}

__global__ void __launch_bounds__(256)
k_gather(int outB, const float* __restrict__ gatb, int l, int N) {
    __shared__ __align__(16) float4 sW[8][32];
    __shared__ int sS[8][32];
    if (blockIdx.x == 0 && threadIdx.x < HC) {
        g_sum[threadIdx.x] = 0.f;
        g_sq[threadIdx.x] = 0.f;
    }
    int wid = threadIdx.x >> 5, lane = threadIdx.x & 31;
    int gw = blockIdx.x * 8 + wid;
    if (gw >= N) return;
    int hd = lane >> 3;
    int start = g_off[gw], end = g_off[gw + 1];
    const float4 ad4 = *reinterpret_cast<const float4*>(&g_ad[gw * NHD]);
    float4 acc = make_float4(0.f, 0.f, 0.f, 0.f);
    float4 wsum4 = make_float4(0.f, 0.f, 0.f, 0.f);
    const float* __restrict__ hbase = g_h;

    for (int base = start; base < end; base += 32) {
        int cnt = min(32, end - base);
        int s_l = 0;
        float4 w4 = make_float4(0.f, 0.f, 0.f, 0.f);
        if (lane < cnt) {
            s_l = g_csrc[base + lane];
            const float4 as4 = *reinterpret_cast<const float4*>(&g_as[s_l * NHD]);
            w4.x = lrelu_exp(as4.x + ad4.x);
            w4.y = lrelu_exp(as4.y + ad4.y);
            w4.z = lrelu_exp(as4.z + ad4.z);
            w4.w = lrelu_exp(as4.w + ad4.w);
        }
        wsum4.x += w4.x; wsum4.y += w4.y; wsum4.z += w4.z; wsum4.w += w4.w;
        sS[wid][lane] = s_l;
        sW[wid][lane] = w4;
        __syncwarp();

        int j = 0;
        for (; j + 4 <= cnt; j += 4) {
            int s0 = sS[wid][j], s1 = sS[wid][j + 1], s2 = sS[wid][j + 2], s3 = sS[wid][j + 3];
            float w0 = reinterpret_cast<const float*>(&sW[wid][j    ])[hd];
            float w1 = reinterpret_cast<const float*>(&sW[wid][j + 1])[hd];
            float w2 = reinterpret_cast<const float*>(&sW[wid][j + 2])[hd];
            float w3 = reinterpret_cast<const float*>(&sW[wid][j + 3])[hd];
            const float4 h0 = *reinterpret_cast<const float4*>(&hbase[s0 * HC + lane * 4]);
            const float4 h1 = *reinterpret_cast<const float4*>(&hbase[s1 * HC + lane * 4]);
            const float4 h2 = *reinterpret_cast<const float4*>(&hbase[s2 * HC + lane * 4]);
            const float4 h3 = *reinterpret_cast<const float4*>(&hbase[s3 * HC + lane * 4]);
            acc.x = fmaf(w0, h0.x, acc.x); acc.y = fmaf(w0, h0.y, acc.y);
            acc.z = fmaf(w0, h0.z, acc.z); acc.w = fmaf(w0, h0.w, acc.w);
            acc.x = fmaf(w1, h1.x, acc.x); acc.y = fmaf(w1, h1.y, acc.y);
            acc.z = fmaf(w1, h1.z, acc.z); acc.w = fmaf(w1, h1.w, acc.w);
            acc.x = fmaf(w2, h2.x, acc.x); acc.y = fmaf(w2, h2.y, acc.y);
            acc.z = fmaf(w2, h2.z, acc.z); acc.w = fmaf(w2, h2.w, acc.w);
            acc.x = fmaf(w3, h3.x, acc.x); acc.y = fmaf(w3, h3.y, acc.y);
            acc.z = fmaf(w3, h3.z, acc.z); acc.w = fmaf(w3, h3.w, acc.w);
        }
        for (; j < cnt; j++) {
            int s = sS[wid][j];
            float w = reinterpret_cast<const float*>(&sW[wid][j])[hd];
            const float4 hv = *reinterpret_cast<const float4*>(&hbase[s * HC + lane * 4]);
            acc.x = fmaf(w, hv.x, acc.x); acc.y = fmaf(w, hv.y, acc.y);
            acc.z = fmaf(w, hv.z, acc.z); acc.w = fmaf(w, hv.w, acc.w);
        }
        __syncwarp();
    }

    // reduce wsum4 across warp (all lanes end with the full per-head sums)
#pragma unroll
    for (int off = 16; off; off >>= 1) {
        wsum4.x += __shfl_xor_sync(0xffffffffu, wsum4.x, off);
        wsum4.y += __shfl_xor_sync(0xffffffffu, wsum4.y, off);
        wsum4.z += __shfl_xor_sync(0xffffffffu, wsum4.z, off);
        wsum4.w += __shfl_xor_sync(0xffffffffu, wsum4.w, off);
    }
    float wsumh = (hd == 0) ? wsum4.x : (hd == 1) ? wsum4.y : (hd == 2) ? wsum4.z : wsum4.w;
    float inv = 1.f / (wsumh + 1e-16f);
    const float4 b4 = *reinterpret_cast<const float4*>(&gatb[l * HC + lane * 4]);
    float4 o = make_float4(fmaf(acc.x, inv, b4.x), fmaf(acc.y, inv, b4.y),
                           fmaf(acc.z, inv, b4.z), fmaf(acc.w, inv, b4.w));
    *reinterpret_cast<float4*>(bufPtr(outB) + gw * HC + lane * 4) = o;
}

// readout: y = x @ W^T + b, warp-aggregated scatter-add into graph bucket
__global__ void k_readout(const float* __restrict__ rW, const float* __restrict__ rb,
                          const int* __restrict__ batch, float* __restrict__ out,
                          int inB, int N) {
    __shared__ float sW[OUTC * HC];
    __shared__ float sb[OUTC];
    int tid = threadIdx.x;
    for (int i = tid; i < OUTC * HC; i += blockDim.x) sW[i] = rW[i];
    if (tid < OUTC) sb[tid] = rb[tid];
    __syncthreads();
    int n = blockIdx.x * blockDim.x + tid;
    bool valid = (n < N);
    float acc[OUTC];
#pragma unroll
    for (int o = 0; o < OUTC; o++) acc[o] = valid ? sb[o] : 0.f;
    if (valid) {
        const float* __restrict__ x = bufPtr(inB) + n * HC;
        for (int k = 0; k < HC; k++) {
            float xk = x[k];
#pragma unroll
            for (int o = 0; o < OUTC; o++) acc[o] = fmaf(xk, sW[o * HC + k], acc[o]);
        }
    }
    int g = valid ? batch[n] : -1;
    int g0 = __shfl_sync(0xffffffffu, g, 0);
    bool uni = __all_sync(0xffffffffu, g == g0);
    int lane = tid & 31;
    if (uni) {
#pragma unroll
        for (int o = 0; o < OUTC; o++) {
            float v = acc[o];
#pragma unroll
            for (int off = 16; off; off >>= 1) v += __shfl_xor_sync(0xffffffffu, v, off);
            if (lane == o) atomicAdd(&out[g * OUTC + o], v);  // spread atomics over lanes
            else if (o >= 32 && lane == o - 32) {}             // (OUTC<32, unreachable)
        }
    } else if (valid) {
#pragma unroll
        for (int o = 0; o < OUTC; o++) atomicAdd(&out[g * OUTC + o], acc[o]);
    }
}

// ---------------- launch ----------------
extern "C" void kernel_launch(void* const* d_in, const int* in_sizes, int n_in,
                              void* d_out, int out_size) {
    const int*   xidx  = (const int*)d_in[0];
    const int*   ei    = (const int*)d_in[1];
    const int*   batch = (const int*)d_in[2];
    const float* embed = (const float*)d_in[3];
    const float* bng   = (const float*)d_in[4];
    const float* bnb   = (const float*)d_in[5];
    const float* linW  = (const float*)d_in[6];
    const float* linb  = (const float*)d_in[7];
    const float* gatW  = (const float*)d_in[8];
    const float* attS  = (const float*)d_in[9];
    const float* attD  = (const float*)d_in[10];
    const float* gatb  = (const float*)d_in[11];
    const float* rW    = (const float*)d_in[12];
    const float* rb    = (const float*)d_in[13];
    float* out = (float*)d_out;

    int N = in_sizes[0];
    int E = in_sizes[1] / 2;
    int tot = E + N;

    k_embed<<<(N * HC + 255) / 256, 256>>>(xidx, embed, N);
    k_hist<<<(tot + 255) / 256, 256>>>(ei, N, E);
    k_scan<<<1, 1024>>>(N, out, out_size);
    k_scatter<<<(tot + 255) / 256, 256>>>(ei, N, E);

    for (int l = 0; l < NL; l++) {
        int inB = l & 1;
        int outB = inB ^ 1;
        k_stats<<<592, 128>>>(inB, N);
        k_node<<<(N + 127) / 128, 128>>>(inB, l, linW, linb, gatW, attS, attD, bng, bnb, N);
        k_gather<<<(N + 7) / 8, 256>>>(outB, gatb, l, N);
    }

    k_readout<<<(N + 127) / 128, 128>>>(rW, rb, batch, out, 1, N);
}

// round 5
// speedup vs baseline: 1.7794x; 1.1494x over previous
#include <cuda_runtime.h>

#define NN     50000
#define EE     800000
#define TOTE   (EE + NN)
#define NHD    4
#define NC     32
#define HC     128
#define NL     3
#define NG     128
#define OUTC   10
#define BN_EPS 1e-5f

// ---------------- static device scratch ----------------
__device__ __align__(16) float g_buf0[NN * HC];
__device__ __align__(16) float g_buf1[NN * HC];
__device__ __align__(16) float g_y[NN * NC];
__device__ __align__(16) float g_as[NN * NHD];
__device__ __align__(16) float g_ad[NN * NHD];
__device__ float g_sumL[NL][HC];
__device__ float g_sqL[NL][HC];
__device__ int   g_deg[NN];
__device__ int   g_off[NN + 1];
__device__ int   g_cur[NN];
__device__ int   g_csrc[TOTE];

__device__ __forceinline__ float* bufPtr(int b) { return b ? g_buf1 : g_buf0; }

// ---------------- kernels ----------------

// zero degree array, all BN-stat buffers, and the output
__global__ void k_init(float* __restrict__ out, int out_n, int N) {
    int gid = blockIdx.x * blockDim.x + threadIdx.x;
    if (gid < N) g_deg[gid] = 0;
    if (gid < NL * HC) { (&g_sumL[0][0])[gid] = 0.f; (&g_sqL[0][0])[gid] = 0.f; }
    if (gid < out_n) out[gid] = 0.f;
}

// x = embed[x_idx] -> buf0, fused layer-0 BN stats + degree histogram
__global__ void __launch_bounds__(1024)
k_embed_hist(const int* __restrict__ xidx, const float* __restrict__ embed,
             const int* __restrict__ ei, int N, int E) {
    __shared__ float sS[HC], sQ[HC];
    int tid = threadIdx.x;
    if (tid < HC) { sS[tid] = 0.f; sQ[tid] = 0.f; }
    __syncthreads();
    long gid = (long)blockIdx.x * 1024 + tid;
    if (gid < (long)N * HC) {
        int n = (int)(gid >> 7), c = (int)(gid & 127);
        float v = embed[xidx[n] * HC + c];
        g_buf0[gid] = v;
        atomicAdd(&sS[c], v);
        atomicAdd(&sQ[c], v * v);
    }
    __syncthreads();
    if (tid < HC) {
        atomicAdd(&g_sumL[0][tid], sS[tid]);
        atomicAdd(&g_sqL[0][tid], sQ[tid]);
    }
    // degree histogram (edges + self loops)
    if (gid < E + N) {
        int d = (gid < E) ? ei[E + gid] : (int)(gid - E);
        atomicAdd(&g_deg[d], 1);
    }
}

// single-block exclusive scan of degrees -> offsets (+ cursor copy)
__global__ void k_scan(int N) {
    __shared__ int ssum[1024];
    int t = threadIdx.x;
    int CH = (N + 1023) / 1024;
    int b = t * CH, e = min(b + CH, N);
    int s = 0;
    for (int i = b; i < e; i++) s += g_deg[i];
    ssum[t] = s;
    __syncthreads();
    for (int off = 1; off < 1024; off <<= 1) {
        int v = (t >= off) ? ssum[t - off] : 0;
        __syncthreads();
        ssum[t] += v;
        __syncthreads();
    }
    int run = ssum[t] - s;
    for (int i = b; i < e; i++) {
        g_off[i] = run;
        g_cur[i] = run;
        run += g_deg[i];
    }
    if (t == 1023) g_off[N] = run;
}

// scatter edge sources into CSR buckets
__global__ void k_scatter(const int* __restrict__ ei, int N, int E) {
    int gid = blockIdx.x * blockDim.x + threadIdx.x;
    if (gid >= E + N) return;
    int s, d;
    if (gid < E) { s = ei[gid]; d = ei[E + gid]; }
    else         { s = d = gid - E; }
    int pos = atomicAdd(&g_cur[d], 1);
    g_csrc[pos] = s;
}

// Per-node: (BN folded into Linear) -> Linear(128->32)+ReLU -> y, plus attention
// logits via precomputed 4x32 matrices A_s = gatW^T att_src, A_d = gatW^T att_dst.
#define SXP 129
__global__ void __launch_bounds__(128)
k_node(int inB, int l,
       const float* __restrict__ linW, const float* __restrict__ linb,
       const float* __restrict__ gatW,
       const float* __restrict__ attS, const float* __restrict__ attD,
       const float* __restrict__ bng, const float* __restrict__ bnb,
       int N) {
    __shared__ __align__(16) float sLinP[NC * HC];   // BN-folded lin_W  [c][k]
    __shared__ __align__(16) float sB[32 * SXP];     // staging tile / y transpose
    __shared__ float sScale[HC], sShift[HC];
    __shared__ float sAs[HC], sAd[HC];               // A_s/A_d: [hd*32+c]
    __shared__ float sConst[NC];

    int tid = threadIdx.x;
    if (tid < HC) {
        float invN = 1.0f / (float)N;
        float mean = g_sumL[l][tid] * invN;
        float var  = g_sqL[l][tid] * invN - mean * mean;
        float rstd = rsqrtf(var + BN_EPS);
        float sc = bng[l * HC + tid] * rstd;
        sScale[tid] = sc;
        sShift[tid] = bnb[l * HC + tid] - sc * mean;
    }
    __syncthreads();
    for (int i = tid; i < NC * HC; i += 128) {
        int k = i & 127;
        sLinP[i] = linW[l * NC * HC + i] * sScale[k];
    }
    if (tid < NC) {
        float cst = linb[l * NC + tid];
        const float* lw = &linW[l * NC * HC + tid * HC];
        for (int k = 0; k < HC; k++) cst += lw[k] * sShift[k];
        sConst[tid] = cst;
    }
    {
        int hd = tid >> 5, cc = tid & 31;
        float a = 0.f, bsum = 0.f;
        for (int j = 0; j < 32; j++) {
            int r = hd * 32 + j;
            float w = __ldg(&gatW[l * HC * NC + r * NC + cc]);
            a    = fmaf(w, __ldg(&attS[l * HC + r]), a);
            bsum = fmaf(w, __ldg(&attD[l * HC + r]), bsum);
        }
        sAs[tid] = a;
        sAd[tid] = bsum;
    }
    __syncthreads();

    int n0 = blockIdx.x * 128;
    int n = n0 + tid;
    const float* __restrict__ xb = bufPtr(inB);

    float y[NC];
#pragma unroll
    for (int c = 0; c < NC; c++) y[c] = sConst[c];

#pragma unroll
    for (int kt = 0; kt < 4; kt++) {
        __syncthreads();
#pragma unroll
        for (int j = 0; j < 32; j++) {
            int i = tid + j * 128;
            int ni = i >> 5, ki = i & 31;
            int k = kt * 32 + ki;
            int nn = n0 + ni;
            float v = (nn < N) ? xb[nn * HC + k] : 0.f;
            sB[ki * SXP + ni] = v;
        }
        __syncthreads();
        float xk[32];
#pragma unroll
        for (int kk = 0; kk < 32; kk++) xk[kk] = sB[kk * SXP + tid];
#pragma unroll
        for (int c = 0; c < NC; c++) {
            const float4* w4 = reinterpret_cast<const float4*>(&sLinP[c * HC + kt * 32]);
            float acc = y[c];
#pragma unroll
            for (int q = 0; q < 8; q++) {
                float4 w = w4[q];
                acc = fmaf(xk[4 * q], w.x, acc);
                acc = fmaf(xk[4 * q + 1], w.y, acc);
                acc = fmaf(xk[4 * q + 2], w.z, acc);
                acc = fmaf(xk[4 * q + 3], w.w, acc);
            }
            y[c] = acc;
        }
    }
#pragma unroll
    for (int c = 0; c < NC; c++) y[c] = fmaxf(y[c], 0.f);

    // store y transposed via SMEM for coalesced global writes
    __syncthreads();
#pragma unroll
    for (int c = 0; c < NC; c++) sB[c * SXP + tid] = y[c];
    __syncthreads();
#pragma unroll
    for (int j = 0; j < 32; j++) {
        int i = tid + j * 128;
        int ni = i >> 5, ci = i & 31;
        int nn = n0 + ni;
        if (nn < N) g_y[nn * NC + ci] = sB[ci * SXP + ni];
    }

    if (n < N) {
        float as[NHD], ad[NHD];
#pragma unroll
        for (int hd = 0; hd < NHD; hd++) {
            float a = 0.f, b = 0.f;
#pragma unroll
            for (int c = 0; c < NC; c++) {
                a = fmaf(y[c], sAs[hd * 32 + c], a);
                b = fmaf(y[c], sAd[hd * 32 + c], b);
            }
            as[hd] = a; ad[hd] = b;
        }
        *reinterpret_cast<float4*>(&g_as[n * NHD]) = make_float4(as[0], as[1], as[2], as[3]);
        *reinterpret_cast<float4*>(&g_ad[n * NHD]) = make_float4(ad[0], ad[1], ad[2], ad[3]);
    }
}

__device__ __forceinline__ float lrelu_exp(float z) {
    z = (z > 0.f) ? z : 0.2f * z;
    return __expf(z);
}

// Gather in y-space (128 B/edge), then per-node projection agg -> out = gatW*agg + b.
// Also accumulates next layer's BN stats.
__global__ void __launch_bounds__(256)
k_gather(int outB, const float* __restrict__ gatW, const float* __restrict__ gatb,
         int l, int N, int accumStats) {
    __shared__ __align__(16) float sGatW[HC * 33];   // [r*33 + c], pad-33
    __shared__ __align__(16) float sAgg[8][HC];
    __shared__ __align__(16) float4 sW[8][32];
    __shared__ int sS[8][32];
    __shared__ float sSt[2][HC];

    int tid = threadIdx.x;
    int wid = tid >> 5, lane = tid & 31;
    for (int m = tid; m < HC * NC; m += 256) {
        int r = m >> 5, c = m & 31;
        sGatW[r * 33 + c] = gatW[l * HC * NC + m];
    }
    if (tid < HC) { sSt[0][tid] = 0.f; sSt[1][tid] = 0.f; }
    __syncthreads();

    int gw = blockIdx.x * 8 + wid;
    int hd = lane >> 3, q = lane & 7;
    float4 acc = make_float4(0.f, 0.f, 0.f, 0.f);

    if (gw < N) {
        int start = g_off[gw], end = g_off[gw + 1];
        const float4 ad4 = *reinterpret_cast<const float4*>(&g_ad[gw * NHD]);
        float4 wsum4 = make_float4(0.f, 0.f, 0.f, 0.f);
        const float* __restrict__ ybase = g_y;

        for (int base = start; base < end; base += 32) {
            int cnt = min(32, end - base);
            int s_l = 0;
            float4 w4 = make_float4(0.f, 0.f, 0.f, 0.f);
            if (lane < cnt) {
                s_l = g_csrc[base + lane];
                const float4 as4 = *reinterpret_cast<const float4*>(&g_as[s_l * NHD]);
                w4.x = lrelu_exp(as4.x + ad4.x);
                w4.y = lrelu_exp(as4.y + ad4.y);
                w4.z = lrelu_exp(as4.z + ad4.z);
                w4.w = lrelu_exp(as4.w + ad4.w);
            }
            wsum4.x += w4.x; wsum4.y += w4.y; wsum4.z += w4.z; wsum4.w += w4.w;
            sS[wid][lane] = s_l;
            sW[wid][lane] = w4;
            __syncwarp();

            int j = 0;
            for (; j + 4 <= cnt; j += 4) {
                int s0 = sS[wid][j], s1 = sS[wid][j + 1], s2 = sS[wid][j + 2], s3 = sS[wid][j + 3];
                float w0 = reinterpret_cast<const float*>(&sW[wid][j    ])[hd];
                float w1 = reinterpret_cast<const float*>(&sW[wid][j + 1])[hd];
                float w2 = reinterpret_cast<const float*>(&sW[wid][j + 2])[hd];
                float w3 = reinterpret_cast<const float*>(&sW[wid][j + 3])[hd];
                const float4 y0 = *reinterpret_cast<const float4*>(&ybase[s0 * NC + q * 4]);
                const float4 y1 = *reinterpret_cast<const float4*>(&ybase[s1 * NC + q * 4]);
                const float4 y2 = *reinterpret_cast<const float4*>(&ybase[s2 * NC + q * 4]);
                const float4 y3 = *reinterpret_cast<const float4*>(&ybase[s3 * NC + q * 4]);
                acc.x = fmaf(w0, y0.x, acc.x); acc.y = fmaf(w0, y0.y, acc.y);
                acc.z = fmaf(w0, y0.z, acc.z); acc.w = fmaf(w0, y0.w, acc.w);
                acc.x = fmaf(w1, y1.x, acc.x); acc.y = fmaf(w1, y1.y, acc.y);
                acc.z = fmaf(w1, y1.z, acc.z); acc.w = fmaf(w1, y1.w, acc.w);
                acc.x = fmaf(w2, y2.x, acc.x); acc.y = fmaf(w2, y2.y, acc.y);
                acc.z = fmaf(w2, y2.z, acc.z); acc.w = fmaf(w2, y2.w, acc.w);
                acc.x = fmaf(w3, y3.x, acc.x); acc.y = fmaf(w3, y3.y, acc.y);
                acc.z = fmaf(w3, y3.z, acc.z); acc.w = fmaf(w3, y3.w, acc.w);
            }
            for (; j < cnt; j++) {
                int s = sS[wid][j];
                float w = reinterpret_cast<const float*>(&sW[wid][j])[hd];
                const float4 yv = *reinterpret_cast<const float4*>(&ybase[s * NC + q * 4]);
                acc.x = fmaf(w, yv.x, acc.x); acc.y = fmaf(w, yv.y, acc.y);
                acc.z = fmaf(w, yv.z, acc.z); acc.w = fmaf(w, yv.w, acc.w);
            }
            __syncwarp();
        }

#pragma unroll
        for (int off = 16; off; off >>= 1) {
            wsum4.x += __shfl_xor_sync(0xffffffffu, wsum4.x, off);
            wsum4.y += __shfl_xor_sync(0xffffffffu, wsum4.y, off);
            wsum4.z += __shfl_xor_sync(0xffffffffu, wsum4.z, off);
            wsum4.w += __shfl_xor_sync(0xffffffffu, wsum4.w, off);
        }
        float wsumh = (hd == 0) ? wsum4.x : (hd == 1) ? wsum4.y : (hd == 2) ? wsum4.z : wsum4.w;
        float inv = 1.f / (wsumh + 1e-16f);
        acc.x *= inv; acc.y *= inv; acc.z *= inv; acc.w *= inv;
    }

    // stash normalized agg (head-major: sAgg[wid][hd*32 + q*4] == [wid][lane*4])
    *reinterpret_cast<float4*>(&sAgg[wid][lane * 4]) = acc;
    __syncwarp();

    // epilogue: out[o] = sum_c gatW[o][c]*agg[head(o)][c] + b[o];  o = lane + 32*i, head(o)=i
    if (gw < N) {
        float* outrow = bufPtr(outB) + gw * HC;
#pragma unroll
        for (int i = 0; i < 4; i++) {
            int o = lane + 32 * i;
            float a = __ldg(&gatb[l * HC + o]);
            const float* aggh = &sAgg[wid][i * 32];
            const float* wrow = &sGatW[o * 33];
#pragma unroll
            for (int c = 0; c < 32; c++) a = fmaf(wrow[c], aggh[c], a);
            outrow[o] = a;
            if (accumStats) {
                atomicAdd(&sSt[0][o], a);
                atomicAdd(&sSt[1][o], a * a);
            }
        }
    }
    if (accumStats) {
        __syncthreads();
        if (tid < HC) {
            atomicAdd(&g_sumL[l + 1][tid], sSt[0][tid]);
            atomicAdd(&g_sqL[l + 1][tid], sSt[1][tid]);
        }
    }
}

// readout: y = x @ W^T + b, warp-aggregated scatter-add into graph bucket
__global__ void k_readout(const float* __restrict__ rW, const float* __restrict__ rb,
                          const int* __restrict__ batch, float* __restrict__ out,
                          int inB, int N) {
    __shared__ float sW[OUTC * HC];
    __shared__ float sb[OUTC];
    int tid = threadIdx.x;
    for (int i = tid; i < OUTC * HC; i += blockDim.x) sW[i] = rW[i];
    if (tid < OUTC) sb[tid] = rb[tid];
    __syncthreads();
    int n = blockIdx.x * blockDim.x + tid;
    bool valid = (n < N);
    float acc[OUTC];
#pragma unroll
    for (int o = 0; o < OUTC; o++) acc[o] = valid ? sb[o] : 0.f;
    if (valid) {
        const float* __restrict__ x = bufPtr(inB) + n * HC;
        for (int k = 0; k < HC; k++) {
            float xk = x[k];
#pragma unroll
            for (int o = 0; o < OUTC; o++) acc[o] = fmaf(xk, sW[o * HC + k], acc[o]);
        }
    }
    int g = valid ? batch[n] : -1;
    int g0 = __shfl_sync(0xffffffffu, g, 0);
    bool uni = __all_sync(0xffffffffu, g == g0);
    int lane = tid & 31;
    if (uni) {
#pragma unroll
        for (int o = 0; o < OUTC; o++) {
            float v = acc[o];
#pragma unroll
            for (int off = 16; off; off >>= 1) v += __shfl_xor_sync(0xffffffffu, v, off);
            if (lane == o) atomicAdd(&out[g * OUTC + o], v);
        }
    } else if (valid) {
#pragma unroll
        for (int o = 0; o < OUTC; o++) atomicAdd(&out[g * OUTC + o], acc[o]);
    }
}

// ---------------- launch ----------------
extern "C" void kernel_launch(void* const* d_in, const int* in_sizes, int n_in,
                              void* d_out, int out_size) {
    const int*   xidx  = (const int*)d_in[0];
    const int*   ei    = (const int*)d_in[1];
    const int*   batch = (const int*)d_in[2];
    const float* embed = (const float*)d_in[3];
    const float* bng   = (const float*)d_in[4];
    const float* bnb   = (const float*)d_in[5];
    const float* linW  = (const float*)d_in[6];
    const float* linb  = (const float*)d_in[7];
    const float* gatW  = (const float*)d_in[8];
    const float* attS  = (const float*)d_in[9];
    const float* attD  = (const float*)d_in[10];
    const float* gatb  = (const float*)d_in[11];
    const float* rW    = (const float*)d_in[12];
    const float* rb    = (const float*)d_in[13];
    float* out = (float*)d_out;

    int N = in_sizes[0];
    int E = in_sizes[1] / 2;
    int tot = E + N;

    k_init<<<(N + 255) / 256, 256>>>(out, out_size, N);
    k_embed_hist<<<((long)N * HC + 1023) / 1024, 1024>>>(xidx, embed, ei, N, E);
    k_scan<<<1, 1024>>>(N);
    k_scatter<<<(tot + 255) / 256, 256>>>(ei, N, E);

    for (int l = 0; l < NL; l++) {
        int inB = l & 1;
        int outB = inB ^ 1;
        k_node<<<(N + 127) / 128, 128>>>(inB, l, linW, linb, gatW, attS, attD, bng, bnb, N);
        k_gather<<<(N + 7) / 8, 256>>>(outB, gatW, gatb, l, N, (l < NL - 1) ? 1 : 0);
    }

    k_readout<<<(N + 127) / 128, 128>>>(rW, rb, batch, out, 1, N);
}

// round 6
// speedup vs baseline: 1.8962x; 1.0656x over previous
#include <cuda_runtime.h>

#define NN     50000
#define EE     800000
#define NHD    4
#define NC     32
#define HC     128
#define NL     3
#define OUTC   10
#define CAP    96
#define BN_EPS 1e-5f

// ---------------- static device scratch ----------------
__device__ __align__(16) float g_buf0[NN * HC];
__device__ __align__(16) float g_buf1[NN * HC];
__device__ __align__(16) float g_y[NN * NC];
__device__ __align__(16) float g_as[NN * NHD];
__device__ __align__(16) float g_ad[NN * NHD];
__device__ float g_sumL[NL][HC];
__device__ float g_sqL[NL][HC];
__device__ int   g_deg[NN];
__device__ int   g_pad[NN * CAP];

__device__ __forceinline__ float* bufPtr(int b) { return b ? g_buf1 : g_buf0; }

__device__ __forceinline__ float lrelu_exp(float z) {
    z = (z > 0.f) ? z : 0.2f * z;
    return __expf(z);
}

// ---------------- kernels ----------------

// zero degree array, BN-stat buffers, output
__global__ void k_init(float* __restrict__ out, int out_n, int N) {
    int gid = blockIdx.x * blockDim.x + threadIdx.x;
    if (gid < N) g_deg[gid] = 0;
    if (gid < NL * HC) { (&g_sumL[0][0])[gid] = 0.f; (&g_sqL[0][0])[gid] = 0.f; }
    if (gid < out_n) out[gid] = 0.f;
}

// Block-range fused: [0,nA): embed gather + layer-0 BN stats.  [nA,...): padded-CSR scatter.
__global__ void __launch_bounds__(256)
k_embed_scatter(const int* __restrict__ xidx, const float* __restrict__ embed,
                const int* __restrict__ ei, int N, int E, int nA) {
    int tid = threadIdx.x;
    if ((int)blockIdx.x < nA) {
        __shared__ float sS[2][HC], sQ[2][HC];
        int c = tid & 127, sub = tid >> 7;
        int r0 = blockIdx.x * 64;
        float s = 0.f, s2 = 0.f;
#pragma unroll 4
        for (int it = 0; it < 32; it++) {
            int r = r0 + sub + it * 2;
            if (r < N) {
                float v = embed[xidx[r] * HC + c];
                g_buf0[r * HC + c] = v;
                s += v; s2 += v * v;
            }
        }
        sS[sub][c] = s; sQ[sub][c] = s2;
        __syncthreads();
        if (tid < HC) {
            atomicAdd(&g_sumL[0][tid], sS[0][tid] + sS[1][tid]);
            atomicAdd(&g_sqL[0][tid], sQ[0][tid] + sQ[1][tid]);
        }
    } else {
        int gid = (blockIdx.x - nA) * 256 + tid;
        if (gid < E) {
            int s = ei[gid], d = ei[E + gid];
            int pos = atomicAdd(&g_deg[d], 1);
            g_pad[d * CAP + pos] = s;
        }
    }
}

// Per-node: BN-folded Linear(128->32)+ReLU -> y; attention logits via 4x32 folded matrices.
#define SXP 129
__global__ void __launch_bounds__(128)
k_node(int inB, int l,
       const float* __restrict__ linW, const float* __restrict__ linb,
       const float* __restrict__ gatW,
       const float* __restrict__ attS, const float* __restrict__ attD,
       const float* __restrict__ bng, const float* __restrict__ bnb,
       int N) {
    __shared__ __align__(16) float sLinP[NC * HC];
    __shared__ __align__(16) float sB[32 * SXP];
    __shared__ float sScale[HC], sShift[HC];
    __shared__ float sAs[HC], sAd[HC];
    __shared__ float sConst[NC];

    int tid = threadIdx.x;
    if (tid < HC) {
        float invN = 1.0f / (float)N;
        float mean = g_sumL[l][tid] * invN;
        float var  = g_sqL[l][tid] * invN - mean * mean;
        float rstd = rsqrtf(var + BN_EPS);
        float sc = bng[l * HC + tid] * rstd;
        sScale[tid] = sc;
        sShift[tid] = bnb[l * HC + tid] - sc * mean;
    }
    __syncthreads();
    for (int i = tid; i < NC * HC; i += 128) {
        int k = i & 127;
        sLinP[i] = linW[l * NC * HC + i] * sScale[k];
    }
    if (tid < NC) {
        float cst = linb[l * NC + tid];
        const float* lw = &linW[l * NC * HC + tid * HC];
        for (int k = 0; k < HC; k++) cst += lw[k] * sShift[k];
        sConst[tid] = cst;
    }
    {
        int hd = tid >> 5, cc = tid & 31;
        float a = 0.f, bsum = 0.f;
        for (int j = 0; j < 32; j++) {
            int r = hd * 32 + j;
            float w = __ldg(&gatW[l * HC * NC + r * NC + cc]);
            a    = fmaf(w, __ldg(&attS[l * HC + r]), a);
            bsum = fmaf(w, __ldg(&attD[l * HC + r]), bsum);
        }
        sAs[tid] = a;
        sAd[tid] = bsum;
    }
    __syncthreads();

    int n0 = blockIdx.x * 128;
    int n = n0 + tid;
    const float* __restrict__ xb = bufPtr(inB);

    float y[NC];
#pragma unroll
    for (int c = 0; c < NC; c++) y[c] = sConst[c];

#pragma unroll
    for (int kt = 0; kt < 4; kt++) {
        __syncthreads();
#pragma unroll
        for (int j = 0; j < 32; j++) {
            int i = tid + j * 128;
            int ni = i >> 5, ki = i & 31;
            int k = kt * 32 + ki;
            int nn = n0 + ni;
            float v = (nn < N) ? xb[nn * HC + k] : 0.f;
            sB[ki * SXP + ni] = v;
        }
        __syncthreads();
        float xk[32];
#pragma unroll
        for (int kk = 0; kk < 32; kk++) xk[kk] = sB[kk * SXP + tid];
#pragma unroll
        for (int c = 0; c < NC; c++) {
            const float4* w4 = reinterpret_cast<const float4*>(&sLinP[c * HC + kt * 32]);
            float acc = y[c];
#pragma unroll
            for (int q = 0; q < 8; q++) {
                float4 w = w4[q];
                acc = fmaf(xk[4 * q], w.x, acc);
                acc = fmaf(xk[4 * q + 1], w.y, acc);
                acc = fmaf(xk[4 * q + 2], w.z, acc);
                acc = fmaf(xk[4 * q + 3], w.w, acc);
            }
            y[c] = acc;
        }
    }
#pragma unroll
    for (int c = 0; c < NC; c++) y[c] = fmaxf(y[c], 0.f);

    // store y transposed via SMEM for coalesced global writes
    __syncthreads();
#pragma unroll
    for (int c = 0; c < NC; c++) sB[c * SXP + tid] = y[c];
    __syncthreads();
#pragma unroll
    for (int j = 0; j < 32; j++) {
        int i = tid + j * 128;
        int ni = i >> 5, ci = i & 31;
        int nn = n0 + ni;
        if (nn < N) g_y[nn * NC + ci] = sB[ci * SXP + ni];
    }

    if (n < N) {
        float as[NHD], ad[NHD];
#pragma unroll
        for (int hd = 0; hd < NHD; hd++) {
            float a = 0.f, b = 0.f;
#pragma unroll
            for (int c = 0; c < NC; c++) {
                a = fmaf(y[c], sAs[hd * 32 + c], a);
                b = fmaf(y[c], sAd[hd * 32 + c], b);
            }
            as[hd] = a; ad[hd] = b;
        }
        *reinterpret_cast<float4*>(&g_as[n * NHD]) = make_float4(as[0], as[1], as[2], as[3]);
        *reinterpret_cast<float4*>(&g_ad[n * NHD]) = make_float4(ad[0], ad[1], ad[2], ad[3]);
    }
}

// Gather in y-space + projection epilogue. mode=0: write node features + BN stats for l+1.
// mode=1 (last layer): fused readout (x@rW^T + rb, segment-sum into out), no feature write.
__global__ void __launch_bounds__(256)
k_gather(int outB, const float* __restrict__ gatW, const float* __restrict__ gatb,
         const float* __restrict__ rW, const float* __restrict__ rb,
         const int* __restrict__ batch, float* __restrict__ out,
         int l, int N, int mode) {
    __shared__ __align__(16) float sGatW[HC * 33];
    __shared__ __align__(16) float4 sW[8][32];
    __shared__ int sS[8][32];
    __shared__ __align__(16) float sOut[8][132];
    __shared__ float sRW[OUTC * HC];

    int tid = threadIdx.x;
    int wid = tid >> 5, lane = tid & 31;
    for (int m = tid; m < HC * NC; m += 256) {
        int r = m >> 5, c = m & 31;
        sGatW[r * 33 + c] = gatW[l * HC * NC + m];
    }
    if (mode == 1)
        for (int m = tid; m < OUTC * HC; m += 256) sRW[m] = rW[m];
    __syncthreads();

    int gw = blockIdx.x * 8 + wid;
    int hd = lane >> 3, q = lane & 7;
    bool valid = (gw < N);
    float4 acc = make_float4(0.f, 0.f, 0.f, 0.f);

    if (valid) {
        int cnt = g_deg[gw];
        const int* __restrict__ lst = &g_pad[gw * CAP];
        const float4 ad4 = *reinterpret_cast<const float4*>(&g_ad[gw * NHD]);
        const float4 asSelf = *reinterpret_cast<const float4*>(&g_as[gw * NHD]);
        float4 wself;
        wself.x = lrelu_exp(asSelf.x + ad4.x);
        wself.y = lrelu_exp(asSelf.y + ad4.y);
        wself.z = lrelu_exp(asSelf.z + ad4.z);
        wself.w = lrelu_exp(asSelf.w + ad4.w);
        float4 wsum4 = make_float4(0.f, 0.f, 0.f, 0.f);
        const float* __restrict__ ybase = g_y;

        for (int base = 0; base < cnt; base += 32) {
            int c2 = min(32, cnt - base);
            int s_l = 0;
            float4 w4 = make_float4(0.f, 0.f, 0.f, 0.f);
            if (lane < c2) {
                s_l = lst[base + lane];
                const float4 as4 = *reinterpret_cast<const float4*>(&g_as[s_l * NHD]);
                w4.x = lrelu_exp(as4.x + ad4.x);
                w4.y = lrelu_exp(as4.y + ad4.y);
                w4.z = lrelu_exp(as4.z + ad4.z);
                w4.w = lrelu_exp(as4.w + ad4.w);
            }
            wsum4.x += w4.x; wsum4.y += w4.y; wsum4.z += w4.z; wsum4.w += w4.w;
            sS[wid][lane] = s_l;
            sW[wid][lane] = w4;
            __syncwarp();

            int j = 0;
            for (; j + 4 <= c2; j += 4) {
                int s0 = sS[wid][j], s1 = sS[wid][j + 1], s2 = sS[wid][j + 2], s3 = sS[wid][j + 3];
                float w0 = reinterpret_cast<const float*>(&sW[wid][j    ])[hd];
                float w1 = reinterpret_cast<const float*>(&sW[wid][j + 1])[hd];
                float w2 = reinterpret_cast<const float*>(&sW[wid][j + 2])[hd];
                float w3 = reinterpret_cast<const float*>(&sW[wid][j + 3])[hd];
                const float4 y0 = *reinterpret_cast<const float4*>(&ybase[s0 * NC + q * 4]);
                const float4 y1 = *reinterpret_cast<const float4*>(&ybase[s1 * NC + q * 4]);
                const float4 y2 = *reinterpret_cast<const float4*>(&ybase[s2 * NC + q * 4]);
                const float4 y3 = *reinterpret_cast<const float4*>(&ybase[s3 * NC + q * 4]);
                acc.x = fmaf(w0, y0.x, acc.x); acc.y = fmaf(w0, y0.y, acc.y);
                acc.z = fmaf(w0, y0.z, acc.z); acc.w = fmaf(w0, y0.w, acc.w);
                acc.x = fmaf(w1, y1.x, acc.x); acc.y = fmaf(w1, y1.y, acc.y);
                acc.z = fmaf(w1, y1.z, acc.z); acc.w = fmaf(w1, y1.w, acc.w);
                acc.x = fmaf(w2, y2.x, acc.x); acc.y = fmaf(w2, y2.y, acc.y);
                acc.z = fmaf(w2, y2.z, acc.z); acc.w = fmaf(w2, y2.w, acc.w);
                acc.x = fmaf(w3, y3.x, acc.x); acc.y = fmaf(w3, y3.y, acc.y);
                acc.z = fmaf(w3, y3.z, acc.z); acc.w = fmaf(w3, y3.w, acc.w);
            }
            for (; j < c2; j++) {
                int s = sS[wid][j];
                float w = reinterpret_cast<const float*>(&sW[wid][j])[hd];
                const float4 yv = *reinterpret_cast<const float4*>(&ybase[s * NC + q * 4]);
                acc.x = fmaf(w, yv.x, acc.x); acc.y = fmaf(w, yv.y, acc.y);
                acc.z = fmaf(w, yv.z, acc.z); acc.w = fmaf(w, yv.w, acc.w);
            }
            __syncwarp();
        }

#pragma unroll
        for (int off = 16; off; off >>= 1) {
            wsum4.x += __shfl_xor_sync(0xffffffffu, wsum4.x, off);
            wsum4.y += __shfl_xor_sync(0xffffffffu, wsum4.y, off);
            wsum4.z += __shfl_xor_sync(0xffffffffu, wsum4.z, off);
            wsum4.w += __shfl_xor_sync(0xffffffffu, wsum4.w, off);
        }
        wsum4.x += wself.x; wsum4.y += wself.y; wsum4.z += wself.z; wsum4.w += wself.w;
        // self contribution
        float wsh = (hd == 0) ? wself.x : (hd == 1) ? wself.y : (hd == 2) ? wself.z : wself.w;
        const float4 ys = *reinterpret_cast<const float4*>(&ybase[gw * NC + q * 4]);
        acc.x = fmaf(wsh, ys.x, acc.x); acc.y = fmaf(wsh, ys.y, acc.y);
        acc.z = fmaf(wsh, ys.z, acc.z); acc.w = fmaf(wsh, ys.w, acc.w);
        float wsumh = (hd == 0) ? wsum4.x : (hd == 1) ? wsum4.y : (hd == 2) ? wsum4.z : wsum4.w;
        float inv = 1.f / (wsumh + 1e-16f);
        acc.x *= inv; acc.y *= inv; acc.z *= inv; acc.w *= inv;
    }

    // stash normalized agg (index lane*4 == hd*32 + q*4)
    *reinterpret_cast<float4*>(&sOut[wid][lane * 4]) = acc;
    __syncwarp();

    // projection: a[i] = gatb[o] + sum_c gatW[o][c]*agg[i*32+c],  o = lane + 32*i (head i)
    float a[4];
#pragma unroll
    for (int i = 0; i < 4; i++) {
        int o = lane + 32 * i;
        float v = valid ? __ldg(&gatb[l * HC + o]) : 0.f;
        const float* aggh = &sOut[wid][i * 32];
        const float* wrow = &sGatW[o * 33];
#pragma unroll
        for (int c = 0; c < 32; c++) v = fmaf(wrow[c], aggh[c], v);
        a[i] = valid ? v : 0.f;
    }
    __syncwarp();
#pragma unroll
    for (int i = 0; i < 4; i++) sOut[wid][lane + 32 * i] = a[i];

    if (mode == 0) {
        if (valid) {
            float* outrow = bufPtr(outB) + gw * HC;
#pragma unroll
            for (int i = 0; i < 4; i++) outrow[lane + 32 * i] = a[i];
        }
        // BN stats for next layer: tree-reduce over the block's 8 nodes, no atom conflicts
        __syncthreads();
        if (tid < HC) {
            float s = 0.f, s2 = 0.f;
#pragma unroll
            for (int w = 0; w < 8; w++) {
                float v = sOut[w][tid];
                s += v; s2 += v * v;
            }
            atomicAdd(&g_sumL[l + 1][tid], s);
            atomicAdd(&g_sqL[l + 1][tid], s2);
        }
    } else if (valid) {
        // fused readout: out10 = a . rW + rb, segment-sum by graph
        int g = batch[gw];
#pragma unroll
        for (int o = 0; o < OUTC; o++) {
            float p = 0.f;
#pragma unroll
            for (int i = 0; i < 4; i++)
                p = fmaf(a[i], sRW[o * HC + lane + 32 * i], p);
#pragma unroll
            for (int off = 16; off; off >>= 1) p += __shfl_xor_sync(0xffffffffu, p, off);
            if (lane == o) atomicAdd(&out[g * OUTC + o], p + __ldg(&rb[o]));
        }
    }
}

// ---------------- launch ----------------
extern "C" void kernel_launch(void* const* d_in, const int* in_sizes, int n_in,
                              void* d_out, int out_size) {
    const int*   xidx  = (const int*)d_in[0];
    const int*   ei    = (const int*)d_in[1];
    const int*   batch = (const int*)d_in[2];
    const float* embed = (const float*)d_in[3];
    const float* bng   = (const float*)d_in[4];
    const float* bnb   = (const float*)d_in[5];
    const float* linW  = (const float*)d_in[6];
    const float* linb  = (const float*)d_in[7];
    const float* gatW  = (const float*)d_in[8];
    const float* attS  = (const float*)d_in[9];
    const float* attD  = (const float*)d_in[10];
    const float* gatb  = (const float*)d_in[11];
    const float* rW    = (const float*)d_in[12];
    const float* rb    = (const float*)d_in[13];
    float* out = (float*)d_out;

    int N = in_sizes[0];
    int E = in_sizes[1] / 2;
    int nA = (N + 63) / 64;
    int nB = (E + 255) / 256;

    k_init<<<(N + 255) / 256, 256>>>(out, out_size, N);
    k_embed_scatter<<<nA + nB, 256>>>(xidx, embed, ei, N, E, nA);

    for (int l = 0; l < NL; l++) {
        int inB = l & 1;
        int outB = inB ^ 1;
        int mode = (l == NL - 1) ? 1 : 0;
        k_node<<<(N + 127) / 128, 128>>>(inB, l, linW, linb, gatW, attS, attD, bng, bnb, N);
        k_gather<<<(N + 7) / 8, 256>>>(outB, gatW, gatb, rW, rb, batch, out, l, N, mode);
    }
}